// round 6
// baseline (speedup 1.0000x reference)
#include <cuda_runtime.h>
#include <cuda_bf16.h>
#include <cstdint>
#include <cstddef>

#define Bz   4
#define Hh   8
#define LQ   1024
#define LK   1024
#define DKk  64
#define DVv  64

// ===================== helpers =====================
__device__ __forceinline__ uint32_t packbf(float lo, float hi) {
    uint32_t r;
    asm("cvt.rn.bf16x2.f32 %0, %1, %2;" : "=r"(r) : "f"(hi), "f"(lo));
    return r;
}
__device__ __forceinline__ float lo_of(float x) {
    return x - __bfloat162float(__float2bfloat16(x));
}
__device__ __forceinline__ void mma16816(float* c,
                                         uint32_t a0, uint32_t a1, uint32_t a2, uint32_t a3,
                                         uint32_t b0, uint32_t b1) {
    asm volatile(
        "mma.sync.aligned.m16n8k16.row.col.f32.bf16.bf16.f32 "
        "{%0,%1,%2,%3}, {%4,%5,%6,%7}, {%8,%9}, {%0,%1,%2,%3};"
        : "+f"(c[0]), "+f"(c[1]), "+f"(c[2]), "+f"(c[3])
        : "r"(a0), "r"(a1), "r"(a2), "r"(a3), "r"(b0), "r"(b1));
}

// smem word layout (uint32 units)
#define QTH_OFF 0          // [128j][36]
#define QTL_OFF 4608
#define VTH_OFF 9216       // [64n][68]
#define VTL_OFF 13568
#define SMEM_WORDS 17920
#define SMEM_BYTES (SMEM_WORDS * 4)
// prologue overlays (words): sA@0(2048) sB@2048(512) sBt@2560(512) sAt@3072(2048)
//                            sT1@5120(1024) sT2@6144(2048) sWc@8192(4096)

__global__ void __launch_bounds__(256, 2)
attn_kernel(const float* __restrict__ q,
            const float* __restrict__ WA,  const float* __restrict__ WB,
            const float* __restrict__ WBt, const float* __restrict__ WAt,
            const float* __restrict__ qt,  const float* __restrict__ v,
            float* __restrict__ attn, float* __restrict__ outp) {
    extern __shared__ uint32_t smw[];
    uint32_t* QTH = smw + QTH_OFF;
    uint32_t* QTL = smw + QTL_OFF;
    uint32_t* VTH = smw + VTH_OFF;
    uint32_t* VTL = smw + VTL_OFF;
    float* sf = (float*)smw;

    const int bid = blockIdx.x;
    const int mt  = bid & 7;
    const int h   = (bid >> 3) & 7;
    const int b   = bid >> 6;
    const int i0  = mt * 128;

    const int t    = threadIdx.x;
    const int w    = t >> 5;
    const int lane = t & 31;
    const int grp  = lane >> 2;
    const int q4   = lane & 3;

    const float* qtp = qt + ((size_t)(b * Hh + h) * DKk) * LK;   // [64][1024]
    const float* vp  = v  + ((size_t)(b * Hh + h) * LK) * DVv;   // [1024][64]
    float* attn_base = attn + ((size_t)(b * Hh + h) * LQ + i0) * (size_t)LK;
    float* out_base  = outp + ((size_t)(b * Hh + h) * LQ + i0) * (size_t)DVv;

    const int rA = w * 16 + grp;
    const int rB = rA + 8;

    // ======== prologue 1: Wc = (A@B@Bt@At)/8 into smem ========
    {
        float* sA  = sf;
        float* sB  = sf + 2048;
        float* sBt = sf + 2560;
        float* sAt = sf + 3072;
        float* sT1 = sf + 5120;
        float* sT2 = sf + 6144;
        float* sWc = sf + 8192;

        for (int i = t; i < 2048; i += 256) sA[i]  = WA [h * 2048 + i];
        for (int i = t; i < 512;  i += 256) sB[i]  = WB [h * 512  + i];
        for (int i = t; i < 512;  i += 256) sBt[i] = WBt[h * 512  + i];
        for (int i = t; i < 2048; i += 256) sAt[i] = WAt[h * 2048 + i];
        __syncthreads();

        #pragma unroll
        for (int i = t; i < 1024; i += 256) {           // T1[64][16]
            int r = i >> 4, c = i & 15;
            float s = 0.f;
            #pragma unroll
            for (int k = 0; k < 32; k++) s += sA[r * 32 + k] * sB[k * 16 + c];
            sT1[i] = s;
        }
        __syncthreads();
        #pragma unroll
        for (int i = t; i < 2048; i += 256) {           // T2[64][32]
            int r = i >> 5, c = i & 31;
            float s = 0.f;
            #pragma unroll
            for (int k = 0; k < 16; k++) s += sT1[r * 16 + k] * sBt[k * 32 + c];
            sT2[i] = s;
        }
        __syncthreads();
        #pragma unroll
        for (int i = t; i < 4096; i += 256) {           // Wc[64k][64d] * 1/8
            int r = i >> 6, c = i & 63;
            float s = 0.f;
            #pragma unroll
            for (int k = 0; k < 32; k++) s += sT2[r * 32 + k] * sAt[k * 64 + c];
            sWc[i] = s * 0.125f;
        }
        __syncthreads();
    }

    // ======== prologue 2: P fragments via MMA (P = Q @ Wc, 3-term) ========
    uint32_t pah[4][4], pal[4][4];
    {
        const float* sWc = sf + 8192;
        // Q A-fragments (hi/lo) straight from gmem
        uint32_t qah[4][4], qal[4][4];
        const float* qr0 = q + ((size_t)(b * LQ + i0 + rA) * Hh + h) * DKk;
        const float* qr1 = q + ((size_t)(b * LQ + i0 + rB) * Hh + h) * DKk;
        #pragma unroll
        for (int kt = 0; kt < 4; kt++) {
            int k = 16 * kt + 2 * q4;
            float2 x0 = *(const float2*)&qr0[k];
            float2 x8 = *(const float2*)&qr0[k + 8];
            float2 y0 = *(const float2*)&qr1[k];
            float2 y8 = *(const float2*)&qr1[k + 8];
            qah[kt][0] = packbf(x0.x, x0.y); qah[kt][1] = packbf(y0.x, y0.y);
            qah[kt][2] = packbf(x8.x, x8.y); qah[kt][3] = packbf(y8.x, y8.y);
            qal[kt][0] = packbf(lo_of(x0.x), lo_of(x0.y));
            qal[kt][1] = packbf(lo_of(y0.x), lo_of(y0.y));
            qal[kt][2] = packbf(lo_of(x8.x), lo_of(x8.y));
            qal[kt][3] = packbf(lo_of(y8.x), lo_of(y8.y));
        }
        #pragma unroll
        for (int kt2 = 0; kt2 < 4; kt2++) {
            float p0[4] = {0.f, 0.f, 0.f, 0.f};
            float p1[4] = {0.f, 0.f, 0.f, 0.f};
            #pragma unroll
            for (int nt2 = 0; nt2 < 2; nt2++) {
                float* pc = nt2 ? p1 : p0;
                const int ncol = 8 * (2 * kt2 + nt2) + grp;
                #pragma unroll
                for (int kq = 0; kq < 4; kq++) {
                    int kk = 16 * kq + 2 * q4;
                    float w0 = sWc[kk * 64 + ncol];
                    float w1 = sWc[(kk + 1) * 64 + ncol];
                    float w8 = sWc[(kk + 8) * 64 + ncol];
                    float w9 = sWc[(kk + 9) * 64 + ncol];
                    uint32_t bh0 = packbf(w0, w1), bh1 = packbf(w8, w9);
                    uint32_t bl0 = packbf(lo_of(w0), lo_of(w1));
                    uint32_t bl1 = packbf(lo_of(w8), lo_of(w9));
                    mma16816(pc, qah[kq][0], qah[kq][1], qah[kq][2], qah[kq][3], bh0, bh1);
                    mma16816(pc, qah[kq][0], qah[kq][1], qah[kq][2], qah[kq][3], bl0, bl1);
                    mma16816(pc, qal[kq][0], qal[kq][1], qal[kq][2], qal[kq][3], bh0, bh1);
                }
            }
            pah[kt2][0] = packbf(p0[0], p0[1]); pah[kt2][1] = packbf(p0[2], p0[3]);
            pah[kt2][2] = packbf(p1[0], p1[1]); pah[kt2][3] = packbf(p1[2], p1[3]);
            pal[kt2][0] = packbf(lo_of(p0[0]), lo_of(p0[1]));
            pal[kt2][1] = packbf(lo_of(p0[2]), lo_of(p0[3]));
            pal[kt2][2] = packbf(lo_of(p1[0]), lo_of(p1[1]));
            pal[kt2][3] = packbf(lo_of(p1[2]), lo_of(p1[3]));
        }
    }

    float m0 = -1e30f, m1 = -1e30f, s0 = 0.f, s1 = 0.f;

    // ================= PASS A: online (max,sum), hi-only MMA =================
    #pragma unroll 1
    for (int ch = 0; ch < 8; ch++) {
        const int j0 = ch * 128;
        __syncthreads();
        #pragma unroll
        for (int it = 0; it < 4; it++) {           // qtT hi (batched float4 loads)
            int idx = t + 256 * it;
            int kp = idx >> 5;
            int jg = (idx & 31) << 2;
            float4 a = *(const float4*)&qtp[(size_t)(2 * kp) * LK + j0 + jg];
            float4 c = *(const float4*)&qtp[(size_t)(2 * kp + 1) * LK + j0 + jg];
            QTH[(jg + 0) * 36 + kp] = packbf(a.x, c.x);
            QTH[(jg + 1) * 36 + kp] = packbf(a.y, c.y);
            QTH[(jg + 2) * 36 + kp] = packbf(a.z, c.z);
            QTH[(jg + 3) * 36 + kp] = packbf(a.w, c.w);
        }
        __syncthreads();

        #pragma unroll
        for (int h2 = 0; h2 < 2; h2++) {
            float acc[8][4];
            #pragma unroll
            for (int nt = 0; nt < 8; nt++) {
                #pragma unroll
                for (int u = 0; u < 4; u++) acc[nt][u] = 0.f;
                const uint32_t* Brow = QTH + (8 * (h2 * 8 + nt) + grp) * 36 + q4;
                #pragma unroll
                for (int kt = 0; kt < 4; kt++)
                    mma16816(acc[nt], pah[kt][0], pah[kt][1], pah[kt][2], pah[kt][3],
                             Brow[8 * kt], Brow[8 * kt + 4]);
            }
            float cm0 = -1e30f, cm1 = -1e30f;
            #pragma unroll
            for (int nt = 0; nt < 8; nt++) {
                cm0 = fmaxf(cm0, fmaxf(acc[nt][0], acc[nt][1]));
                cm1 = fmaxf(cm1, fmaxf(acc[nt][2], acc[nt][3]));
            }
            cm0 = fmaxf(cm0, __shfl_xor_sync(0xffffffffu, cm0, 1));
            cm0 = fmaxf(cm0, __shfl_xor_sync(0xffffffffu, cm0, 2));
            cm1 = fmaxf(cm1, __shfl_xor_sync(0xffffffffu, cm1, 1));
            cm1 = fmaxf(cm1, __shfl_xor_sync(0xffffffffu, cm1, 2));
            float nm0 = fmaxf(m0, cm0), nm1 = fmaxf(m1, cm1);
            float sn0 = 0.f, sn1 = 0.f;
            #pragma unroll
            for (int nt = 0; nt < 8; nt++) {
                sn0 += __expf(acc[nt][0] - nm0) + __expf(acc[nt][1] - nm0);
                sn1 += __expf(acc[nt][2] - nm1) + __expf(acc[nt][3] - nm1);
            }
            sn0 += __shfl_xor_sync(0xffffffffu, sn0, 1);
            sn0 += __shfl_xor_sync(0xffffffffu, sn0, 2);
            sn1 += __shfl_xor_sync(0xffffffffu, sn1, 1);
            sn1 += __shfl_xor_sync(0xffffffffu, sn1, 2);
            s0 = s0 * __expf(m0 - nm0) + sn0;  m0 = nm0;
            s1 = s1 * __expf(m1 - nm1) + sn1;  m1 = nm1;
        }
    }
    const float is0 = 1.f / s0;
    const float is1 = 1.f / s1;

    // ================= PASS B: 3-term S, attn out, O += E@V =================
    float oacc[8][4];
    #pragma unroll
    for (int nt = 0; nt < 8; nt++)
        #pragma unroll
        for (int u = 0; u < 4; u++) oacc[nt][u] = 0.f;

    #pragma unroll 1
    for (int ch = 0; ch < 8; ch++) {
        const int j0 = ch * 128;
        __syncthreads();
        #pragma unroll
        for (int it = 0; it < 4; it++) {           // qtT hi+lo
            int idx = t + 256 * it;
            int kp = idx >> 5;
            int jg = (idx & 31) << 2;
            float4 a = *(const float4*)&qtp[(size_t)(2 * kp) * LK + j0 + jg];
            float4 c = *(const float4*)&qtp[(size_t)(2 * kp + 1) * LK + j0 + jg];
            QTH[(jg + 0) * 36 + kp] = packbf(a.x, c.x);
            QTH[(jg + 1) * 36 + kp] = packbf(a.y, c.y);
            QTH[(jg + 2) * 36 + kp] = packbf(a.z, c.z);
            QTH[(jg + 3) * 36 + kp] = packbf(a.w, c.w);
            QTL[(jg + 0) * 36 + kp] = packbf(lo_of(a.x), lo_of(c.x));
            QTL[(jg + 1) * 36 + kp] = packbf(lo_of(a.y), lo_of(c.y));
            QTL[(jg + 2) * 36 + kp] = packbf(lo_of(a.z), lo_of(c.z));
            QTL[(jg + 3) * 36 + kp] = packbf(lo_of(a.w), lo_of(c.w));
        }
        #pragma unroll
        for (int it = 0; it < 4; it++) {           // VT hi+lo
            int idx = t + 256 * it;
            int jp = idx >> 4;
            int ng = (idx & 15) << 2;
            float4 a = *(const float4*)&vp[(size_t)(j0 + 2 * jp) * DVv + ng];
            float4 c = *(const float4*)&vp[(size_t)(j0 + 2 * jp + 1) * DVv + ng];
            VTH[(ng + 0) * 68 + jp] = packbf(a.x, c.x);
            VTH[(ng + 1) * 68 + jp] = packbf(a.y, c.y);
            VTH[(ng + 2) * 68 + jp] = packbf(a.z, c.z);
            VTH[(ng + 3) * 68 + jp] = packbf(a.w, c.w);
            VTL[(ng + 0) * 68 + jp] = packbf(lo_of(a.x), lo_of(c.x));
            VTL[(ng + 1) * 68 + jp] = packbf(lo_of(a.y), lo_of(c.y));
            VTL[(ng + 2) * 68 + jp] = packbf(lo_of(a.z), lo_of(c.z));
            VTL[(ng + 3) * 68 + jp] = packbf(lo_of(a.w), lo_of(c.w));
        }
        __syncthreads();

        #pragma unroll
        for (int h2 = 0; h2 < 2; h2++) {
            float acc[8][4];
            #pragma unroll
            for (int nt = 0; nt < 8; nt++) {
                #pragma unroll
                for (int u = 0; u < 4; u++) acc[nt][u] = 0.f;
                const uint32_t* Bh = QTH + (8 * (h2 * 8 + nt) + grp) * 36 + q4;
                const uint32_t* Bl = QTL + (8 * (h2 * 8 + nt) + grp) * 36 + q4;
                #pragma unroll
                for (int kt = 0; kt < 4; kt++) {
                    uint32_t bh0 = Bh[8 * kt], bh1 = Bh[8 * kt + 4];
                    uint32_t bl0 = Bl[8 * kt], bl1 = Bl[8 * kt + 4];
                    mma16816(acc[nt], pah[kt][0], pah[kt][1], pah[kt][2], pah[kt][3], bh0, bh1);
                    mma16816(acc[nt], pah[kt][0], pah[kt][1], pah[kt][2], pah[kt][3], bl0, bl1);
                    mma16816(acc[nt], pal[kt][0], pal[kt][1], pal[kt][2], pal[kt][3], bh0, bh1);
                }
            }

            #pragma unroll
            for (int kt2 = 0; kt2 < 4; kt2++) {
                const int t0 = 2 * kt2, t1 = 2 * kt2 + 1;
                float e00 = __expf(acc[t0][0] - m0) * is0;
                float e01 = __expf(acc[t0][1] - m0) * is0;
                float e02 = __expf(acc[t0][2] - m1) * is1;
                float e03 = __expf(acc[t0][3] - m1) * is1;
                float e10 = __expf(acc[t1][0] - m0) * is0;
                float e11 = __expf(acc[t1][1] - m0) * is0;
                float e12 = __expf(acc[t1][2] - m1) * is1;
                float e13 = __expf(acc[t1][3] - m1) * is1;

                const int cb = j0 + h2 * 64 + 16 * kt2 + 2 * q4;
                *(float2*)&attn_base[(size_t)rA * LK + cb]     = make_float2(e00, e01);
                *(float2*)&attn_base[(size_t)rB * LK + cb]     = make_float2(e02, e03);
                *(float2*)&attn_base[(size_t)rA * LK + cb + 8] = make_float2(e10, e11);
                *(float2*)&attn_base[(size_t)rB * LK + cb + 8] = make_float2(e12, e13);

                uint32_t eh0 = packbf(e00, e01), eh1 = packbf(e02, e03);
                uint32_t eh2 = packbf(e10, e11), eh3 = packbf(e12, e13);
                uint32_t el0 = packbf(lo_of(e00), lo_of(e01));
                uint32_t el1 = packbf(lo_of(e02), lo_of(e03));
                uint32_t el2 = packbf(lo_of(e10), lo_of(e11));
                uint32_t el3 = packbf(lo_of(e12), lo_of(e13));

                const int jpb = 32 * h2 + 8 * kt2 + q4;
                #pragma unroll
                for (int nt = 0; nt < 8; nt++) {
                    const uint32_t* Vh = VTH + (8 * nt + grp) * 68 + jpb;
                    const uint32_t* Vl = VTL + (8 * nt + grp) * 68 + jpb;
                    uint32_t vh0 = Vh[0], vh1 = Vh[4];
                    uint32_t vl0 = Vl[0], vl1 = Vl[4];
                    mma16816(oacc[nt], eh0, eh1, eh2, eh3, vh0, vh1);
                    mma16816(oacc[nt], eh0, eh1, eh2, eh3, vl0, vl1);
                    mma16816(oacc[nt], el0, el1, el2, el3, vh0, vh1);
                }
            }
        }
    }

    // ================= epilogue: O store =================
    #pragma unroll
    for (int nt = 0; nt < 8; nt++) {
        *(float2*)&out_base[(size_t)rA * DVv + 8 * nt + 2 * q4] =
            make_float2(oacc[nt][0], oacc[nt][1]);
        *(float2*)&out_base[(size_t)rB * DVv + 8 * nt + 2 * q4] =
            make_float2(oacc[nt][2], oacc[nt][3]);
    }
}

// ===================== launch =====================
extern "C" void kernel_launch(void* const* d_in, const int* in_sizes, int n_in,
                              void* d_out, int out_size) {
    const float* q   = (const float*)d_in[0];
    const float* WA  = (const float*)d_in[1];
    const float* WB  = (const float*)d_in[2];
    const float* WAt = (const float*)d_in[3];
    const float* WBt = (const float*)d_in[4];
    const float* qt  = (const float*)d_in[5];
    const float* v   = (const float*)d_in[6];

    float* outp = (float*)d_out;
    const size_t attn_elems = (size_t)Bz * Hh * LQ * LK;
    float* attn = outp + ((size_t)out_size - attn_elems);

    cudaFuncSetAttribute(attn_kernel, cudaFuncAttributeMaxDynamicSharedMemorySize,
                         SMEM_BYTES);

    attn_kernel<<<Bz * Hh * 8, 256, SMEM_BYTES>>>(q, WA, WB, WBt, WAt, qt, v, attn, outp);
}

// round 7
// speedup vs baseline: 1.2440x; 1.2440x over previous
#include <cuda_runtime.h>
#include <cuda_bf16.h>
#include <cstdint>
#include <cstddef>

#define Bz   4
#define Hh   8
#define LQ   1024
#define LK   1024
#define DKk  64
#define DVv  64

// packed MMA-fragment blobs: [bh(32)][ch(8)][4096 words]
__device__ uint32_t g_QTH[32 * 8 * 4096];
__device__ uint32_t g_QTL[32 * 8 * 4096];
__device__ uint32_t g_VTH[32 * 8 * 4096];
__device__ uint32_t g_VTL[32 * 8 * 4096];

// ===================== helpers =====================
__device__ __forceinline__ uint32_t packbf(float lo, float hi) {
    uint32_t r;
    asm("cvt.rn.bf16x2.f32 %0, %1, %2;" : "=r"(r) : "f"(hi), "f"(lo));
    return r;
}
__device__ __forceinline__ float lo_of(float x) {
    return x - __bfloat162float(__float2bfloat16(x));
}
__device__ __forceinline__ void mma16816(float* c,
                                         uint32_t a0, uint32_t a1, uint32_t a2, uint32_t a3,
                                         uint32_t b0, uint32_t b1) {
    asm volatile(
        "mma.sync.aligned.m16n8k16.row.col.f32.bf16.bf16.f32 "
        "{%0,%1,%2,%3}, {%4,%5,%6,%7}, {%8,%9}, {%0,%1,%2,%3};"
        : "+f"(c[0]), "+f"(c[1]), "+f"(c[2]), "+f"(c[3])
        : "r"(a0), "r"(a1), "r"(a2), "r"(a3), "r"(b0), "r"(b1));
}

// ===================== Kernel 0: fragment pre-pack =====================
// grid = 32 bh * 8 ch, 256 threads.
// qt blob word (j, w): w = kt*8 + q4*2 + u  <->  kp = 8*kt + q4 + 4*u
//   value = pack(qt[2kp][j0+j], qt[2kp+1][j0+j])
// v blob word (n, w): w = h2*32 + kt2*8 + q4*2 + u <-> jp = 32*h2+8*kt2+q4+4*u
//   value = pack(v[j0+2jp][n], v[j0+2jp+1][n])
__global__ void __launch_bounds__(256) pack_kernel(const float* __restrict__ qt,
                                                   const float* __restrict__ v) {
    __shared__ uint32_t sh[4096], sl[4096];
    const int bh = blockIdx.x >> 3;
    const int ch = blockIdx.x & 7;
    const int j0 = ch * 128;
    const int t  = threadIdx.x;

    const float* qtp = qt + (size_t)bh * DKk * LK;
    const float* vp  = v  + (size_t)bh * LK * DVv;

    // ---- qt phase ----
    {
        const int j    = t & 127;
        const int half = t >> 7;
        #pragma unroll
        for (int i = 0; i < 16; i++) {
            int kp = half * 16 + i;
            float f0 = qtp[(size_t)(2 * kp) * LK + j0 + j];
            float f1 = qtp[(size_t)(2 * kp + 1) * LK + j0 + j];
            int kt = kp >> 3, r = kp & 7;
            int q4r = r & 3, u = r >> 2;
            int w = kt * 8 + q4r * 2 + u;
            sh[j * 32 + w] = packbf(f0, f1);
            sl[j * 32 + w] = packbf(lo_of(f0), lo_of(f1));
        }
    }
    __syncthreads();
    {
        uint4* dH = (uint4*)(g_QTH + (size_t)blockIdx.x * 4096);
        uint4* dL = (uint4*)(g_QTL + (size_t)blockIdx.x * 4096);
        #pragma unroll
        for (int i = 0; i < 4; i++) {
            int idx = t + 256 * i;
            dH[idx] = ((const uint4*)sh)[idx];
            dL[idx] = ((const uint4*)sl)[idx];
        }
    }
    __syncthreads();

    // ---- v phase ----
    {
        const int n  = t & 63;
        const int qr = t >> 6;
        #pragma unroll
        for (int i = 0; i < 16; i++) {
            int jp = qr * 16 + i;
            float f0 = vp[(size_t)(j0 + 2 * jp) * DVv + n];
            float f1 = vp[(size_t)(j0 + 2 * jp + 1) * DVv + n];
            int h2 = jp >> 5, r = jp & 31;
            int kt2 = r >> 3, rr = r & 7;
            int q4r = rr & 3, u = rr >> 2;
            int w = h2 * 32 + kt2 * 8 + q4r * 2 + u;
            sh[n * 64 + w] = packbf(f0, f1);
            sl[n * 64 + w] = packbf(lo_of(f0), lo_of(f1));
        }
    }
    __syncthreads();
    {
        uint4* dH = (uint4*)(g_VTH + (size_t)blockIdx.x * 4096);
        uint4* dL = (uint4*)(g_VTL + (size_t)blockIdx.x * 4096);
        #pragma unroll
        for (int i = 0; i < 4; i++) {
            int idx = t + 256 * i;
            dH[idx] = ((const uint4*)sh)[idx];
            dL[idx] = ((const uint4*)sl)[idx];
        }
    }
}

// ===================== Kernel 1: attention =====================
// smem word layout: QTH@0 [128j][40]  QTL@5120 [128j][40]
//                   VTH@10240 [64n][72]  VTL@14848 [64n][72]
#define QTH_OFF 0
#define QTL_OFF 5120
#define VTH_OFF 10240
#define VTL_OFF 14848
#define SMEM_WORDS 19456
#define SMEM_BYTES (SMEM_WORDS * 4)
// prologue float overlays: sA@0(2048) sB@2048(512) sBt@2560(512) sAt@3072(2048)
//                          sT1@5120(1024) sT2@6144(2048) sWc@8192(4096)

__global__ void __launch_bounds__(256, 2)
attn_kernel(const float* __restrict__ q,
            const float* __restrict__ WA,  const float* __restrict__ WB,
            const float* __restrict__ WBt, const float* __restrict__ WAt,
            float* __restrict__ attn, float* __restrict__ outp) {
    extern __shared__ uint32_t smw[];
    uint32_t* QTH = smw + QTH_OFF;
    uint32_t* QTL = smw + QTL_OFF;
    uint32_t* VTH = smw + VTH_OFF;
    uint32_t* VTL = smw + VTL_OFF;
    float* sf = (float*)smw;

    const int bid = blockIdx.x;
    const int mt  = bid & 7;
    const int h   = (bid >> 3) & 7;
    const int b   = bid >> 6;
    const int bh  = b * Hh + h;
    const int i0  = mt * 128;

    const int t    = threadIdx.x;
    const int w    = t >> 5;
    const int lane = t & 31;
    const int grp  = lane >> 2;
    const int q4   = lane & 3;

    float* attn_base = attn + ((size_t)bh * LQ + i0) * (size_t)LK;
    float* out_base  = outp + ((size_t)bh * LQ + i0) * (size_t)DVv;

    const int rA = w * 16 + grp;
    const int rB = rA + 8;

    // ======== prologue 1: Wc = (A@B@Bt@At)/8 into smem ========
    {
        float* sA  = sf;
        float* sB  = sf + 2048;
        float* sBt = sf + 2560;
        float* sAt = sf + 3072;
        float* sT1 = sf + 5120;
        float* sT2 = sf + 6144;
        float* sWc = sf + 8192;

        for (int i = t; i < 2048; i += 256) sA[i]  = WA [h * 2048 + i];
        for (int i = t; i < 512;  i += 256) sB[i]  = WB [h * 512  + i];
        for (int i = t; i < 512;  i += 256) sBt[i] = WBt[h * 512  + i];
        for (int i = t; i < 2048; i += 256) sAt[i] = WAt[h * 2048 + i];
        __syncthreads();

        #pragma unroll
        for (int i = t; i < 1024; i += 256) {
            int r = i >> 4, c = i & 15;
            float s = 0.f;
            #pragma unroll
            for (int k = 0; k < 32; k++) s += sA[r * 32 + k] * sB[k * 16 + c];
            sT1[i] = s;
        }
        __syncthreads();
        #pragma unroll
        for (int i = t; i < 2048; i += 256) {
            int r = i >> 5, c = i & 31;
            float s = 0.f;
            #pragma unroll
            for (int k = 0; k < 16; k++) s += sT1[r * 16 + k] * sBt[k * 32 + c];
            sT2[i] = s;
        }
        __syncthreads();
        #pragma unroll
        for (int i = t; i < 4096; i += 256) {
            int r = i >> 6, c = i & 63;
            float s = 0.f;
            #pragma unroll
            for (int k = 0; k < 32; k++) s += sT2[r * 32 + k] * sAt[k * 64 + c];
            sWc[i] = s * 0.125f;
        }
        __syncthreads();
    }

    // ======== prologue 2: P fragments via MMA (P = Q @ Wc, 3-term) ========
    uint32_t pah[4][4], pal[4][4];
    {
        const float* sWc = sf + 8192;
        uint32_t qah[4][4], qal[4][4];
        const float* qr0 = q + ((size_t)(b * LQ + i0 + rA) * Hh + h) * DKk;
        const float* qr1 = q + ((size_t)(b * LQ + i0 + rB) * Hh + h) * DKk;
        #pragma unroll
        for (int kt = 0; kt < 4; kt++) {
            int k = 16 * kt + 2 * q4;
            float2 x0 = *(const float2*)&qr0[k];
            float2 x8 = *(const float2*)&qr0[k + 8];
            float2 y0 = *(const float2*)&qr1[k];
            float2 y8 = *(const float2*)&qr1[k + 8];
            qah[kt][0] = packbf(x0.x, x0.y); qah[kt][1] = packbf(y0.x, y0.y);
            qah[kt][2] = packbf(x8.x, x8.y); qah[kt][3] = packbf(y8.x, y8.y);
            qal[kt][0] = packbf(lo_of(x0.x), lo_of(x0.y));
            qal[kt][1] = packbf(lo_of(y0.x), lo_of(y0.y));
            qal[kt][2] = packbf(lo_of(x8.x), lo_of(x8.y));
            qal[kt][3] = packbf(lo_of(y8.x), lo_of(y8.y));
        }
        #pragma unroll
        for (int kt2 = 0; kt2 < 4; kt2++) {
            float p0[4] = {0.f, 0.f, 0.f, 0.f};
            float p1[4] = {0.f, 0.f, 0.f, 0.f};
            #pragma unroll
            for (int nt2 = 0; nt2 < 2; nt2++) {
                float* pc = nt2 ? p1 : p0;
                const int ncol = 8 * (2 * kt2 + nt2) + grp;
                #pragma unroll
                for (int kq = 0; kq < 4; kq++) {
                    int kk = 16 * kq + 2 * q4;
                    float w0 = sWc[kk * 64 + ncol];
                    float w1 = sWc[(kk + 1) * 64 + ncol];
                    float w8 = sWc[(kk + 8) * 64 + ncol];
                    float w9 = sWc[(kk + 9) * 64 + ncol];
                    uint32_t bh0 = packbf(w0, w1), bh1 = packbf(w8, w9);
                    uint32_t bl0 = packbf(lo_of(w0), lo_of(w1));
                    uint32_t bl1 = packbf(lo_of(w8), lo_of(w9));
                    mma16816(pc, qah[kq][0], qah[kq][1], qah[kq][2], qah[kq][3], bh0, bh1);
                    mma16816(pc, qah[kq][0], qah[kq][1], qah[kq][2], qah[kq][3], bl0, bl1);
                    mma16816(pc, qal[kq][0], qal[kq][1], qal[kq][2], qal[kq][3], bh0, bh1);
                }
            }
            pah[kt2][0] = packbf(p0[0], p0[1]); pah[kt2][1] = packbf(p0[2], p0[3]);
            pah[kt2][2] = packbf(p1[0], p1[1]); pah[kt2][3] = packbf(p1[2], p1[3]);
            pal[kt2][0] = packbf(lo_of(p0[0]), lo_of(p0[1]));
            pal[kt2][1] = packbf(lo_of(p0[2]), lo_of(p0[3]));
            pal[kt2][2] = packbf(lo_of(p1[0]), lo_of(p1[1]));
            pal[kt2][3] = packbf(lo_of(p1[2]), lo_of(p1[3]));
        }
    }

    float m0 = -1e30f, m1 = -1e30f, s0 = 0.f, s1 = 0.f;

    // ================= PASS A: online (max,sum), hi-only MMA =================
    #pragma unroll 1
    for (int ch = 0; ch < 8; ch++) {
        __syncthreads();
        {
            const uint4* srcH = (const uint4*)(g_QTH + (size_t)(bh * 8 + ch) * 4096);
            #pragma unroll
            for (int it = 0; it < 4; it++) {
                int idx = t + 256 * it;
                int j = idx >> 3, wg = idx & 7;
                *(uint4*)&QTH[j * 40 + wg * 4] = srcH[idx];
            }
        }
        __syncthreads();

        #pragma unroll
        for (int h2 = 0; h2 < 2; h2++) {
            float acc[8][4];
            #pragma unroll
            for (int nt = 0; nt < 8; nt++) {
                #pragma unroll
                for (int u = 0; u < 4; u++) acc[nt][u] = 0.f;
                const uint32_t* Brow = QTH + (8 * (h2 * 8 + nt) + grp) * 40 + q4 * 2;
                #pragma unroll
                for (int kt = 0; kt < 4; kt++) {
                    uint2 bb = *(const uint2*)&Brow[kt * 8];
                    mma16816(acc[nt], pah[kt][0], pah[kt][1], pah[kt][2], pah[kt][3],
                             bb.x, bb.y);
                }
            }
            float cm0 = -1e30f, cm1 = -1e30f;
            #pragma unroll
            for (int nt = 0; nt < 8; nt++) {
                cm0 = fmaxf(cm0, fmaxf(acc[nt][0], acc[nt][1]));
                cm1 = fmaxf(cm1, fmaxf(acc[nt][2], acc[nt][3]));
            }
            cm0 = fmaxf(cm0, __shfl_xor_sync(0xffffffffu, cm0, 1));
            cm0 = fmaxf(cm0, __shfl_xor_sync(0xffffffffu, cm0, 2));
            cm1 = fmaxf(cm1, __shfl_xor_sync(0xffffffffu, cm1, 1));
            cm1 = fmaxf(cm1, __shfl_xor_sync(0xffffffffu, cm1, 2));
            float nm0 = fmaxf(m0, cm0), nm1 = fmaxf(m1, cm1);
            float sn0 = 0.f, sn1 = 0.f;
            #pragma unroll
            for (int nt = 0; nt < 8; nt++) {
                sn0 += __expf(acc[nt][0] - nm0) + __expf(acc[nt][1] - nm0);
                sn1 += __expf(acc[nt][2] - nm1) + __expf(acc[nt][3] - nm1);
            }
            sn0 += __shfl_xor_sync(0xffffffffu, sn0, 1);
            sn0 += __shfl_xor_sync(0xffffffffu, sn0, 2);
            sn1 += __shfl_xor_sync(0xffffffffu, sn1, 1);
            sn1 += __shfl_xor_sync(0xffffffffu, sn1, 2);
            s0 = s0 * __expf(m0 - nm0) + sn0;  m0 = nm0;
            s1 = s1 * __expf(m1 - nm1) + sn1;  m1 = nm1;
        }
    }
    const float is0 = 1.f / s0;
    const float is1 = 1.f / s1;

    // ================= PASS B: 3-term S, attn out, O += E@V =================
    float oacc[8][4];
    #pragma unroll
    for (int nt = 0; nt < 8; nt++)
        #pragma unroll
        for (int u = 0; u < 4; u++) oacc[nt][u] = 0.f;

    #pragma unroll 1
    for (int ch = 0; ch < 8; ch++) {
        const int j0 = ch * 128;
        __syncthreads();
        {
            const size_t blob = (size_t)(bh * 8 + ch) * 4096;
            const uint4* sQH = (const uint4*)(g_QTH + blob);
            const uint4* sQL = (const uint4*)(g_QTL + blob);
            const uint4* sVH = (const uint4*)(g_VTH + blob);
            const uint4* sVL = (const uint4*)(g_VTL + blob);
            #pragma unroll
            for (int it = 0; it < 4; it++) {
                int idx = t + 256 * it;
                int j = idx >> 3, wg = idx & 7;
                *(uint4*)&QTH[j * 40 + wg * 4] = sQH[idx];
                *(uint4*)&QTL[j * 40 + wg * 4] = sQL[idx];
                int n = idx >> 4, wv = idx & 15;
                *(uint4*)&VTH[n * 72 + wv * 4] = sVH[idx];
                *(uint4*)&VTL[n * 72 + wv * 4] = sVL[idx];
            }
        }
        __syncthreads();

        #pragma unroll
        for (int h2 = 0; h2 < 2; h2++) {
            float acc[8][4];
            #pragma unroll
            for (int nt = 0; nt < 8; nt++) {
                #pragma unroll
                for (int u = 0; u < 4; u++) acc[nt][u] = 0.f;
                const uint32_t* Bh = QTH + (8 * (h2 * 8 + nt) + grp) * 40 + q4 * 2;
                const uint32_t* Bl = QTL + (8 * (h2 * 8 + nt) + grp) * 40 + q4 * 2;
                #pragma unroll
                for (int kt = 0; kt < 4; kt++) {
                    uint2 bhp = *(const uint2*)&Bh[kt * 8];
                    uint2 blp = *(const uint2*)&Bl[kt * 8];
                    mma16816(acc[nt], pah[kt][0], pah[kt][1], pah[kt][2], pah[kt][3],
                             bhp.x, bhp.y);
                    mma16816(acc[nt], pah[kt][0], pah[kt][1], pah[kt][2], pah[kt][3],
                             blp.x, blp.y);
                    mma16816(acc[nt], pal[kt][0], pal[kt][1], pal[kt][2], pal[kt][3],
                             bhp.x, bhp.y);
                }
            }

            #pragma unroll
            for (int kt2 = 0; kt2 < 4; kt2++) {
                const int t0 = 2 * kt2, t1 = 2 * kt2 + 1;
                float e00 = __expf(acc[t0][0] - m0) * is0;
                float e01 = __expf(acc[t0][1] - m0) * is0;
                float e02 = __expf(acc[t0][2] - m1) * is1;
                float e03 = __expf(acc[t0][3] - m1) * is1;
                float e10 = __expf(acc[t1][0] - m0) * is0;
                float e11 = __expf(acc[t1][1] - m0) * is0;
                float e12 = __expf(acc[t1][2] - m1) * is1;
                float e13 = __expf(acc[t1][3] - m1) * is1;

                const int cb = j0 + h2 * 64 + 16 * kt2 + 2 * q4;
                *(float2*)&attn_base[(size_t)rA * LK + cb]     = make_float2(e00, e01);
                *(float2*)&attn_base[(size_t)rB * LK + cb]     = make_float2(e02, e03);
                *(float2*)&attn_base[(size_t)rA * LK + cb + 8] = make_float2(e10, e11);
                *(float2*)&attn_base[(size_t)rB * LK + cb + 8] = make_float2(e12, e13);

                uint32_t eh0 = packbf(e00, e01), eh1 = packbf(e02, e03);
                uint32_t eh2 = packbf(e10, e11), eh3 = packbf(e12, e13);
                uint32_t el0 = packbf(lo_of(e00), lo_of(e01));
                uint32_t el1 = packbf(lo_of(e02), lo_of(e03));
                uint32_t el2 = packbf(lo_of(e10), lo_of(e11));
                uint32_t el3 = packbf(lo_of(e12), lo_of(e13));

                const int wv = h2 * 32 + kt2 * 8 + q4 * 2;
                #pragma unroll
                for (int nt = 0; nt < 8; nt++) {
                    uint2 vh = *(const uint2*)&VTH[(8 * nt + grp) * 72 + wv];
                    uint2 vl = *(const uint2*)&VTL[(8 * nt + grp) * 72 + wv];
                    mma16816(oacc[nt], eh0, eh1, eh2, eh3, vh.x, vh.y);
                    mma16816(oacc[nt], eh0, eh1, eh2, eh3, vl.x, vl.y);
                    mma16816(oacc[nt], el0, el1, el2, el3, vh.x, vh.y);
                }
            }
        }
    }

    // ================= epilogue: O store =================
    #pragma unroll
    for (int nt = 0; nt < 8; nt++) {
        *(float2*)&out_base[(size_t)rA * DVv + 8 * nt + 2 * q4] =
            make_float2(oacc[nt][0], oacc[nt][1]);
        *(float2*)&out_base[(size_t)rB * DVv + 8 * nt + 2 * q4] =
            make_float2(oacc[nt][2], oacc[nt][3]);
    }
}

// ===================== launch =====================
extern "C" void kernel_launch(void* const* d_in, const int* in_sizes, int n_in,
                              void* d_out, int out_size) {
    const float* q   = (const float*)d_in[0];
    const float* WA  = (const float*)d_in[1];
    const float* WB  = (const float*)d_in[2];
    const float* WAt = (const float*)d_in[3];
    const float* WBt = (const float*)d_in[4];
    const float* qt  = (const float*)d_in[5];
    const float* v   = (const float*)d_in[6];

    float* outp = (float*)d_out;
    const size_t attn_elems = (size_t)Bz * Hh * LQ * LK;
    float* attn = outp + ((size_t)out_size - attn_elems);

    cudaFuncSetAttribute(attn_kernel, cudaFuncAttributeMaxDynamicSharedMemorySize,
                         SMEM_BYTES);

    pack_kernel<<<Bz * Hh * 8, 256>>>(qt, v);
    attn_kernel<<<Bz * Hh * 8, 256, SMEM_BYTES>>>(q, WA, WB, WBt, WAt, attn, outp);
}

// round 8
// speedup vs baseline: 1.6294x; 1.3098x over previous
#include <cuda_runtime.h>
#include <cuda_bf16.h>
#include <cuda_fp16.h>
#include <cstdint>
#include <cstddef>

#define Bz   4
#define Hh   8
#define LQ   1024
#define LK   1024
#define DKk  64
#define DVv  64

// packed MMA-fragment blobs (fp16x2 hi only): [bh(32)][ch(8)][4096 words]
__device__ uint32_t g_QTH[32 * 8 * 4096];
__device__ uint32_t g_VTH[32 * 8 * 4096];

// ===================== helpers =====================
__device__ __forceinline__ uint32_t packhf(float lo, float hi) {
    __half2 p = __floats2half2_rn(lo, hi);   // .x -> low 16 bits
    return *(uint32_t*)&p;
}
__device__ __forceinline__ float lo_of(float x) {
    return x - __half2float(__float2half_rn(x));
}
__device__ __forceinline__ void mma16816(float* c,
                                         uint32_t a0, uint32_t a1, uint32_t a2, uint32_t a3,
                                         uint32_t b0, uint32_t b1) {
    asm volatile(
        "mma.sync.aligned.m16n8k16.row.col.f32.f16.f16.f32 "
        "{%0,%1,%2,%3}, {%4,%5,%6,%7}, {%8,%9}, {%0,%1,%2,%3};"
        : "+f"(c[0]), "+f"(c[1]), "+f"(c[2]), "+f"(c[3])
        : "r"(a0), "r"(a1), "r"(a2), "r"(a3), "r"(b0), "r"(b1));
}

// ===================== Kernel 0: fragment pre-pack (hi only) =====================
__global__ void __launch_bounds__(256) pack_kernel(const float* __restrict__ qt,
                                                   const float* __restrict__ v) {
    __shared__ uint32_t sh[4096];
    const int bh = blockIdx.x >> 3;
    const int ch = blockIdx.x & 7;
    const int j0 = ch * 128;
    const int t  = threadIdx.x;

    const float* qtp = qt + (size_t)bh * DKk * LK;
    const float* vp  = v  + (size_t)bh * LK * DVv;

    // ---- qt phase ----
    {
        const int j    = t & 127;
        const int half = t >> 7;
        #pragma unroll
        for (int i = 0; i < 16; i++) {
            int kp = half * 16 + i;
            float f0 = qtp[(size_t)(2 * kp) * LK + j0 + j];
            float f1 = qtp[(size_t)(2 * kp + 1) * LK + j0 + j];
            int kt = kp >> 3, r = kp & 7;
            int q4r = r & 3, u = r >> 2;
            int w = kt * 8 + q4r * 2 + u;
            sh[j * 32 + w] = packhf(f0, f1);
        }
    }
    __syncthreads();
    {
        uint4* dH = (uint4*)(g_QTH + (size_t)blockIdx.x * 4096);
        #pragma unroll
        for (int i = 0; i < 4; i++) {
            int idx = t + 256 * i;
            dH[idx] = ((const uint4*)sh)[idx];
        }
    }
    __syncthreads();

    // ---- v phase ----
    {
        const int n  = t & 63;
        const int qr = t >> 6;
        #pragma unroll
        for (int i = 0; i < 16; i++) {
            int jp = qr * 16 + i;
            float f0 = vp[(size_t)(j0 + 2 * jp) * DVv + n];
            float f1 = vp[(size_t)(j0 + 2 * jp + 1) * DVv + n];
            int h2 = jp >> 5, r = jp & 31;
            int kt2 = r >> 3, rr = r & 7;
            int q4r = rr & 3, u = rr >> 2;
            int w = h2 * 32 + kt2 * 8 + q4r * 2 + u;
            sh[n * 64 + w] = packhf(f0, f1);
        }
    }
    __syncthreads();
    {
        uint4* dH = (uint4*)(g_VTH + (size_t)blockIdx.x * 4096);
        #pragma unroll
        for (int i = 0; i < 4; i++) {
            int idx = t + 256 * i;
            dH[idx] = ((const uint4*)sh)[idx];
        }
    }
}

// ===================== Kernel 1: attention =====================
// smem words: QTH@0 [128j][40], VTH@5120 [64n][72]  (9728 words)
// prologue fp32 overlays: sA@0(2048) sB@2048(512) sBt@2560(512) sAt@3072(2048)
//                         sT1@5120(1024) sT2@6144(2048) sWc@8192(4096) -> 12288 words
#define QTH_OFF 0
#define VTH_OFF 5120
#define SMEM_WORDS 12288
#define SMEM_BYTES (SMEM_WORDS * 4)

__global__ void __launch_bounds__(256, 2)
attn_kernel(const float* __restrict__ q,
            const float* __restrict__ WA,  const float* __restrict__ WB,
            const float* __restrict__ WBt, const float* __restrict__ WAt,
            float* __restrict__ attn, float* __restrict__ outp) {
    extern __shared__ uint32_t smw[];
    uint32_t* QTH = smw + QTH_OFF;
    uint32_t* VTH = smw + VTH_OFF;
    float* sf = (float*)smw;

    const int bid = blockIdx.x;
    const int mt  = bid & 7;
    const int h   = (bid >> 3) & 7;
    const int b   = bid >> 6;
    const int bh  = b * Hh + h;
    const int i0  = mt * 128;

    const int t    = threadIdx.x;
    const int w    = t >> 5;
    const int lane = t & 31;
    const int grp  = lane >> 2;
    const int q4   = lane & 3;

    float* attn_base = attn + ((size_t)bh * LQ + i0) * (size_t)LK;
    float* out_base  = outp + ((size_t)bh * LQ + i0) * (size_t)DVv;

    const int rA = w * 16 + grp;
    const int rB = rA + 8;

    // ======== prologue 1: Wc = (A@B@Bt@At)/8 into smem ========
    {
        float* sA  = sf;
        float* sB  = sf + 2048;
        float* sBt = sf + 2560;
        float* sAt = sf + 3072;
        float* sT1 = sf + 5120;
        float* sT2 = sf + 6144;
        float* sWc = sf + 8192;

        for (int i = t; i < 2048; i += 256) sA[i]  = WA [h * 2048 + i];
        for (int i = t; i < 512;  i += 256) sB[i]  = WB [h * 512  + i];
        for (int i = t; i < 512;  i += 256) sBt[i] = WBt[h * 512  + i];
        for (int i = t; i < 2048; i += 256) sAt[i] = WAt[h * 2048 + i];
        __syncthreads();

        #pragma unroll
        for (int i = t; i < 1024; i += 256) {
            int r = i >> 4, c = i & 15;
            float s = 0.f;
            #pragma unroll
            for (int k = 0; k < 32; k++) s += sA[r * 32 + k] * sB[k * 16 + c];
            sT1[i] = s;
        }
        __syncthreads();
        #pragma unroll
        for (int i = t; i < 2048; i += 256) {
            int r = i >> 5, c = i & 31;
            float s = 0.f;
            #pragma unroll
            for (int k = 0; k < 16; k++) s += sT1[r * 16 + k] * sBt[k * 32 + c];
            sT2[i] = s;
        }
        __syncthreads();
        #pragma unroll
        for (int i = t; i < 4096; i += 256) {
            int r = i >> 6, c = i & 63;
            float s = 0.f;
            #pragma unroll
            for (int k = 0; k < 32; k++) s += sT2[r * 32 + k] * sAt[k * 64 + c];
            sWc[i] = s * 0.125f;
        }
        __syncthreads();
    }

    // ======== prologue 2: P fragments via MMA (P = Q @ Wc, 3-term fp16) ========
    uint32_t pah[4][4], pal[4][4];
    {
        const float* sWc = sf + 8192;
        uint32_t qah[4][4], qal[4][4];
        const float* qr0 = q + ((size_t)(b * LQ + i0 + rA) * Hh + h) * DKk;
        const float* qr1 = q + ((size_t)(b * LQ + i0 + rB) * Hh + h) * DKk;
        #pragma unroll
        for (int kt = 0; kt < 4; kt++) {
            int k = 16 * kt + 2 * q4;
            float2 x0 = *(const float2*)&qr0[k];
            float2 x8 = *(const float2*)&qr0[k + 8];
            float2 y0 = *(const float2*)&qr1[k];
            float2 y8 = *(const float2*)&qr1[k + 8];
            qah[kt][0] = packhf(x0.x, x0.y); qah[kt][1] = packhf(y0.x, y0.y);
            qah[kt][2] = packhf(x8.x, x8.y); qah[kt][3] = packhf(y8.x, y8.y);
            qal[kt][0] = packhf(lo_of(x0.x), lo_of(x0.y));
            qal[kt][1] = packhf(lo_of(y0.x), lo_of(y0.y));
            qal[kt][2] = packhf(lo_of(x8.x), lo_of(x8.y));
            qal[kt][3] = packhf(lo_of(y8.x), lo_of(y8.y));
        }
        #pragma unroll
        for (int kt2 = 0; kt2 < 4; kt2++) {
            float p0[4] = {0.f, 0.f, 0.f, 0.f};
            float p1[4] = {0.f, 0.f, 0.f, 0.f};
            #pragma unroll
            for (int nt2 = 0; nt2 < 2; nt2++) {
                float* pc = nt2 ? p1 : p0;
                const int ncol = 8 * (2 * kt2 + nt2) + grp;
                #pragma unroll
                for (int kq = 0; kq < 4; kq++) {
                    int kk = 16 * kq + 2 * q4;
                    float w0 = sWc[kk * 64 + ncol];
                    float w1 = sWc[(kk + 1) * 64 + ncol];
                    float w8 = sWc[(kk + 8) * 64 + ncol];
                    float w9 = sWc[(kk + 9) * 64 + ncol];
                    uint32_t bh0 = packhf(w0, w1), bh1 = packhf(w8, w9);
                    uint32_t bl0 = packhf(lo_of(w0), lo_of(w1));
                    uint32_t bl1 = packhf(lo_of(w8), lo_of(w9));
                    mma16816(pc, qah[kq][0], qah[kq][1], qah[kq][2], qah[kq][3], bh0, bh1);
                    mma16816(pc, qah[kq][0], qah[kq][1], qah[kq][2], qah[kq][3], bl0, bl1);
                    mma16816(pc, qal[kq][0], qal[kq][1], qal[kq][2], qal[kq][3], bh0, bh1);
                }
            }
            pah[kt2][0] = packhf(p0[0], p0[1]); pah[kt2][1] = packhf(p0[2], p0[3]);
            pah[kt2][2] = packhf(p1[0], p1[1]); pah[kt2][3] = packhf(p1[2], p1[3]);
            pal[kt2][0] = packhf(lo_of(p0[0]), lo_of(p0[1]));
            pal[kt2][1] = packhf(lo_of(p0[2]), lo_of(p0[3]));
            pal[kt2][2] = packhf(lo_of(p1[0]), lo_of(p1[1]));
            pal[kt2][3] = packhf(lo_of(p1[2]), lo_of(p1[3]));
        }
    }

    float m0 = -1e30f, m1 = -1e30f, s0 = 0.f, s1 = 0.f;

    // ================= PASS A: online (max,sum), hi-only (1 MMA) =================
    #pragma unroll 1
    for (int ch = 0; ch < 8; ch++) {
        __syncthreads();
        {
            const uint4* srcH = (const uint4*)(g_QTH + (size_t)(bh * 8 + ch) * 4096);
            #pragma unroll
            for (int it = 0; it < 4; it++) {
                int idx = t + 256 * it;
                int j = idx >> 3, wg = idx & 7;
                *(uint4*)&QTH[j * 40 + wg * 4] = srcH[idx];
            }
        }
        __syncthreads();

        #pragma unroll
        for (int h2 = 0; h2 < 2; h2++) {
            float acc[8][4];
            #pragma unroll
            for (int nt = 0; nt < 8; nt++) {
                #pragma unroll
                for (int u = 0; u < 4; u++) acc[nt][u] = 0.f;
                const uint32_t* Brow = QTH + (8 * (h2 * 8 + nt) + grp) * 40 + q4 * 2;
                #pragma unroll
                for (int kt = 0; kt < 4; kt++) {
                    uint2 bb = *(const uint2*)&Brow[kt * 8];
                    mma16816(acc[nt], pah[kt][0], pah[kt][1], pah[kt][2], pah[kt][3],
                             bb.x, bb.y);
                }
            }
            float cm0 = -1e30f, cm1 = -1e30f;
            #pragma unroll
            for (int nt = 0; nt < 8; nt++) {
                cm0 = fmaxf(cm0, fmaxf(acc[nt][0], acc[nt][1]));
                cm1 = fmaxf(cm1, fmaxf(acc[nt][2], acc[nt][3]));
            }
            cm0 = fmaxf(cm0, __shfl_xor_sync(0xffffffffu, cm0, 1));
            cm0 = fmaxf(cm0, __shfl_xor_sync(0xffffffffu, cm0, 2));
            cm1 = fmaxf(cm1, __shfl_xor_sync(0xffffffffu, cm1, 1));
            cm1 = fmaxf(cm1, __shfl_xor_sync(0xffffffffu, cm1, 2));
            float nm0 = fmaxf(m0, cm0), nm1 = fmaxf(m1, cm1);
            float sn0 = 0.f, sn1 = 0.f;
            #pragma unroll
            for (int nt = 0; nt < 8; nt++) {
                sn0 += __expf(acc[nt][0] - nm0) + __expf(acc[nt][1] - nm0);
                sn1 += __expf(acc[nt][2] - nm1) + __expf(acc[nt][3] - nm1);
            }
            sn0 += __shfl_xor_sync(0xffffffffu, sn0, 1);
            sn0 += __shfl_xor_sync(0xffffffffu, sn0, 2);
            sn1 += __shfl_xor_sync(0xffffffffu, sn1, 1);
            sn1 += __shfl_xor_sync(0xffffffffu, sn1, 2);
            s0 = s0 * __expf(m0 - nm0) + sn0;  m0 = nm0;
            s1 = s1 * __expf(m1 - nm1) + sn1;  m1 = nm1;
        }
    }
    const float is0 = 1.f / s0;
    const float is1 = 1.f / s1;

    // ================= PASS B: 2-term S, attn out, O += E@V (E unnormalized) =====
    float oacc[8][4];
    #pragma unroll
    for (int nt = 0; nt < 8; nt++)
        #pragma unroll
        for (int u = 0; u < 4; u++) oacc[nt][u] = 0.f;

    #pragma unroll 1
    for (int ch = 0; ch < 8; ch++) {
        const int j0 = ch * 128;
        __syncthreads();
        {
            const size_t blob = (size_t)(bh * 8 + ch) * 4096;
            const uint4* sQH = (const uint4*)(g_QTH + blob);
            const uint4* sVH = (const uint4*)(g_VTH + blob);
            #pragma unroll
            for (int it = 0; it < 4; it++) {
                int idx = t + 256 * it;
                int j = idx >> 3, wg = idx & 7;
                *(uint4*)&QTH[j * 40 + wg * 4] = sQH[idx];
                int n = idx >> 4, wv = idx & 15;
                *(uint4*)&VTH[n * 72 + wv * 4] = sVH[idx];
            }
        }
        __syncthreads();

        #pragma unroll
        for (int h2 = 0; h2 < 2; h2++) {
            float acc[8][4];
            #pragma unroll
            for (int nt = 0; nt < 8; nt++) {
                #pragma unroll
                for (int u = 0; u < 4; u++) acc[nt][u] = 0.f;
                const uint32_t* Bh = QTH + (8 * (h2 * 8 + nt) + grp) * 40 + q4 * 2;
                #pragma unroll
                for (int kt = 0; kt < 4; kt++) {
                    uint2 bhp = *(const uint2*)&Bh[kt * 8];
                    mma16816(acc[nt], pah[kt][0], pah[kt][1], pah[kt][2], pah[kt][3],
                             bhp.x, bhp.y);
                    mma16816(acc[nt], pal[kt][0], pal[kt][1], pal[kt][2], pal[kt][3],
                             bhp.x, bhp.y);
                }
            }

            #pragma unroll
            for (int kt2 = 0; kt2 < 4; kt2++) {
                const int t0 = 2 * kt2, t1 = 2 * kt2 + 1;
                // unnormalized exps (for O MMA)
                float e00 = __expf(acc[t0][0] - m0);
                float e01 = __expf(acc[t0][1] - m0);
                float e02 = __expf(acc[t0][2] - m1);
                float e03 = __expf(acc[t0][3] - m1);
                float e10 = __expf(acc[t1][0] - m0);
                float e11 = __expf(acc[t1][1] - m0);
                float e12 = __expf(acc[t1][2] - m1);
                float e13 = __expf(acc[t1][3] - m1);

                const int cb = j0 + h2 * 64 + 16 * kt2 + 2 * q4;
                *(float2*)&attn_base[(size_t)rA * LK + cb]     = make_float2(e00 * is0, e01 * is0);
                *(float2*)&attn_base[(size_t)rB * LK + cb]     = make_float2(e02 * is1, e03 * is1);
                *(float2*)&attn_base[(size_t)rA * LK + cb + 8] = make_float2(e10 * is0, e11 * is0);
                *(float2*)&attn_base[(size_t)rB * LK + cb + 8] = make_float2(e12 * is1, e13 * is1);

                uint32_t eh0 = packhf(e00, e01), eh1 = packhf(e02, e03);
                uint32_t eh2 = packhf(e10, e11), eh3 = packhf(e12, e13);
                uint32_t el0 = packhf(lo_of(e00), lo_of(e01));
                uint32_t el1 = packhf(lo_of(e02), lo_of(e03));
                uint32_t el2 = packhf(lo_of(e10), lo_of(e11));
                uint32_t el3 = packhf(lo_of(e12), lo_of(e13));

                const int wv = h2 * 32 + kt2 * 8 + q4 * 2;
                #pragma unroll
                for (int nt = 0; nt < 8; nt++) {
                    uint2 vh = *(const uint2*)&VTH[(8 * nt + grp) * 72 + wv];
                    mma16816(oacc[nt], eh0, eh1, eh2, eh3, vh.x, vh.y);
                    mma16816(oacc[nt], el0, el1, el2, el3, vh.x, vh.y);
                }
            }
        }
    }

    // ================= epilogue: scale by 1/sigma and store O =================
    #pragma unroll
    for (int nt = 0; nt < 8; nt++) {
        *(float2*)&out_base[(size_t)rA * DVv + 8 * nt + 2 * q4] =
            make_float2(oacc[nt][0] * is0, oacc[nt][1] * is0);
        *(float2*)&out_base[(size_t)rB * DVv + 8 * nt + 2 * q4] =
            make_float2(oacc[nt][2] * is1, oacc[nt][3] * is1);
    }
}

// ===================== launch =====================
extern "C" void kernel_launch(void* const* d_in, const int* in_sizes, int n_in,
                              void* d_out, int out_size) {
    const float* q   = (const float*)d_in[0];
    const float* WA  = (const float*)d_in[1];
    const float* WB  = (const float*)d_in[2];
    const float* WAt = (const float*)d_in[3];
    const float* WBt = (const float*)d_in[4];
    const float* qt  = (const float*)d_in[5];
    const float* v   = (const float*)d_in[6];

    float* outp = (float*)d_out;
    const size_t attn_elems = (size_t)Bz * Hh * LQ * LK;
    float* attn = outp + ((size_t)out_size - attn_elems);

    cudaFuncSetAttribute(attn_kernel, cudaFuncAttributeMaxDynamicSharedMemorySize,
                         SMEM_BYTES);

    pack_kernel<<<Bz * Hh * 8, 256>>>(qt, v);
    attn_kernel<<<Bz * Hh * 8, 256, SMEM_BYTES>>>(q, WA, WB, WBt, WAt, attn, outp);
}

// round 9
// speedup vs baseline: 1.7795x; 1.0921x over previous
#include <cuda_runtime.h>
#include <cuda_bf16.h>
#include <cuda_fp16.h>
#include <cstdint>
#include <cstddef>

#define Bz   4
#define Hh   8
#define LQ   1024
#define LK   1024
#define DKk  64
#define DVv  64

// packed MMA-fragment blobs (fp16x2 hi only): [bh(32)][ch(8)][4096 words]
__device__ uint32_t g_QTH[32 * 8 * 4096];
__device__ uint32_t g_VTH[32 * 8 * 4096];

// ===================== helpers =====================
__device__ __forceinline__ uint32_t packhf(float lo, float hi) {
    __half2 p = __floats2half2_rn(lo, hi);   // .x -> low 16 bits
    return *(uint32_t*)&p;
}
__device__ __forceinline__ float lo_of(float x) {
    return x - __half2float(__float2half_rn(x));
}
__device__ __forceinline__ void mma16816(float* c,
                                         uint32_t a0, uint32_t a1, uint32_t a2, uint32_t a3,
                                         uint32_t b0, uint32_t b1) {
    asm volatile(
        "mma.sync.aligned.m16n8k16.row.col.f32.f16.f16.f32 "
        "{%0,%1,%2,%3}, {%4,%5,%6,%7}, {%8,%9}, {%0,%1,%2,%3};"
        : "+f"(c[0]), "+f"(c[1]), "+f"(c[2]), "+f"(c[3])
        : "r"(a0), "r"(a1), "r"(a2), "r"(a3), "r"(b0), "r"(b1));
}

// ===================== Kernel 0: fragment pre-pack (hi only) =====================
// Q blob word for kp (kt=kp>>3, r=kp&7, q4=r&3, u=r>>2):
//   w = (kt>>1)*16 + q4*4 + (kt&1)*2 + u      (kt-pairs adjacent for LDS.128)
// V blob word for jp: w = h2*32 + kt2*8 + q4*2 + u   (unchanged)
__global__ void __launch_bounds__(256) pack_kernel(const float* __restrict__ qt,
                                                   const float* __restrict__ v) {
    __shared__ uint32_t sh[4096];
    const int bh = blockIdx.x >> 3;
    const int ch = blockIdx.x & 7;
    const int j0 = ch * 128;
    const int t  = threadIdx.x;

    const float* qtp = qt + (size_t)bh * DKk * LK;
    const float* vp  = v  + (size_t)bh * LK * DVv;

    // ---- qt phase ----
    {
        const int j    = t & 127;
        const int half = t >> 7;
        #pragma unroll
        for (int i = 0; i < 16; i++) {
            int kp = half * 16 + i;
            float f0 = qtp[(size_t)(2 * kp) * LK + j0 + j];
            float f1 = qtp[(size_t)(2 * kp + 1) * LK + j0 + j];
            int kt = kp >> 3, r = kp & 7;
            int q4r = r & 3, u = r >> 2;
            int w = (kt >> 1) * 16 + q4r * 4 + (kt & 1) * 2 + u;
            sh[j * 32 + w] = packhf(f0, f1);
        }
    }
    __syncthreads();
    {
        uint4* dH = (uint4*)(g_QTH + (size_t)blockIdx.x * 4096);
        #pragma unroll
        for (int i = 0; i < 4; i++) {
            int idx = t + 256 * i;
            dH[idx] = ((const uint4*)sh)[idx];
        }
    }
    __syncthreads();

    // ---- v phase ----
    {
        const int n  = t & 63;
        const int qr = t >> 6;
        #pragma unroll
        for (int i = 0; i < 16; i++) {
            int jp = qr * 16 + i;
            float f0 = vp[(size_t)(j0 + 2 * jp) * DVv + n];
            float f1 = vp[(size_t)(j0 + 2 * jp + 1) * DVv + n];
            int h2 = jp >> 5, r = jp & 31;
            int kt2 = r >> 3, rr = r & 7;
            int q4r = rr & 3, u = rr >> 2;
            int w = h2 * 32 + kt2 * 8 + q4r * 2 + u;
            sh[n * 64 + w] = packhf(f0, f1);
        }
    }
    __syncthreads();
    {
        uint4* dH = (uint4*)(g_VTH + (size_t)blockIdx.x * 4096);
        #pragma unroll
        for (int i = 0; i < 4; i++) {
            int idx = t + 256 * i;
            dH[idx] = ((const uint4*)sh)[idx];
        }
    }
}

// ===================== Kernel 1: attention =====================
// smem words: QTH@0 [128j][48] (6144), VTH@6144 [64n][72] (4608) -> 10752
// prologue fp32 overlays need 12288 words; SMEM_WORDS = 12288
#define QTH_OFF 0
#define VTH_OFF 6144
#define SMEM_WORDS 12288
#define SMEM_BYTES (SMEM_WORDS * 4)

__global__ void __launch_bounds__(256, 2)
attn_kernel(const float* __restrict__ q,
            const float* __restrict__ WA,  const float* __restrict__ WB,
            const float* __restrict__ WBt, const float* __restrict__ WAt,
            float* __restrict__ attn, float* __restrict__ outp) {
    extern __shared__ uint32_t smw[];
    uint32_t* QTH = smw + QTH_OFF;
    uint32_t* VTH = smw + VTH_OFF;
    float* sf = (float*)smw;

    const int bid = blockIdx.x;
    const int mt  = bid & 7;
    const int h   = (bid >> 3) & 7;
    const int b   = bid >> 6;
    const int bh  = b * Hh + h;
    const int i0  = mt * 128;

    const int t    = threadIdx.x;
    const int w    = t >> 5;
    const int lane = t & 31;
    const int grp  = lane >> 2;
    const int q4   = lane & 3;

    float* attn_base = attn + ((size_t)bh * LQ + i0) * (size_t)LK;
    float* out_base  = outp + ((size_t)bh * LQ + i0) * (size_t)DVv;

    const int rA = w * 16 + grp;
    const int rB = rA + 8;

    // ======== prologue 1: Wc = (A@B@Bt@At)/8 into smem ========
    {
        float* sA  = sf;
        float* sB  = sf + 2048;
        float* sBt = sf + 2560;
        float* sAt = sf + 3072;
        float* sT1 = sf + 5120;
        float* sT2 = sf + 6144;
        float* sWc = sf + 8192;

        for (int i = t; i < 2048; i += 256) sA[i]  = WA [h * 2048 + i];
        for (int i = t; i < 512;  i += 256) sB[i]  = WB [h * 512  + i];
        for (int i = t; i < 512;  i += 256) sBt[i] = WBt[h * 512  + i];
        for (int i = t; i < 2048; i += 256) sAt[i] = WAt[h * 2048 + i];
        __syncthreads();

        #pragma unroll
        for (int i = t; i < 1024; i += 256) {
            int r = i >> 4, c = i & 15;
            float s = 0.f;
            #pragma unroll
            for (int k = 0; k < 32; k++) s += sA[r * 32 + k] * sB[k * 16 + c];
            sT1[i] = s;
        }
        __syncthreads();
        #pragma unroll
        for (int i = t; i < 2048; i += 256) {
            int r = i >> 5, c = i & 31;
            float s = 0.f;
            #pragma unroll
            for (int k = 0; k < 16; k++) s += sT1[r * 16 + k] * sBt[k * 32 + c];
            sT2[i] = s;
        }
        __syncthreads();
        #pragma unroll
        for (int i = t; i < 4096; i += 256) {
            int r = i >> 6, c = i & 63;
            float s = 0.f;
            #pragma unroll
            for (int k = 0; k < 32; k++) s += sT2[r * 32 + k] * sAt[k * 64 + c];
            sWc[i] = s * 0.125f;
        }
        __syncthreads();
    }

    // ======== prologue 2: P fragments via MMA (P = Q @ Wc, 3-term fp16) ========
    uint32_t pah[4][4], pal[4][4];
    {
        const float* sWc = sf + 8192;
        uint32_t qah[4][4], qal[4][4];
        const float* qr0 = q + ((size_t)(b * LQ + i0 + rA) * Hh + h) * DKk;
        const float* qr1 = q + ((size_t)(b * LQ + i0 + rB) * Hh + h) * DKk;
        #pragma unroll
        for (int kt = 0; kt < 4; kt++) {
            int k = 16 * kt + 2 * q4;
            float2 x0 = *(const float2*)&qr0[k];
            float2 x8 = *(const float2*)&qr0[k + 8];
            float2 y0 = *(const float2*)&qr1[k];
            float2 y8 = *(const float2*)&qr1[k + 8];
            qah[kt][0] = packhf(x0.x, x0.y); qah[kt][1] = packhf(y0.x, y0.y);
            qah[kt][2] = packhf(x8.x, x8.y); qah[kt][3] = packhf(y8.x, y8.y);
            qal[kt][0] = packhf(lo_of(x0.x), lo_of(x0.y));
            qal[kt][1] = packhf(lo_of(y0.x), lo_of(y0.y));
            qal[kt][2] = packhf(lo_of(x8.x), lo_of(x8.y));
            qal[kt][3] = packhf(lo_of(y8.x), lo_of(y8.y));
        }
        #pragma unroll
        for (int kt2 = 0; kt2 < 4; kt2++) {
            float p0[4] = {0.f, 0.f, 0.f, 0.f};
            float p1[4] = {0.f, 0.f, 0.f, 0.f};
            #pragma unroll
            for (int nt2 = 0; nt2 < 2; nt2++) {
                float* pc = nt2 ? p1 : p0;
                const int ncol = 8 * (2 * kt2 + nt2) + grp;
                #pragma unroll
                for (int kq = 0; kq < 4; kq++) {
                    int kk = 16 * kq + 2 * q4;
                    float w0 = sWc[kk * 64 + ncol];
                    float w1 = sWc[(kk + 1) * 64 + ncol];
                    float w8 = sWc[(kk + 8) * 64 + ncol];
                    float w9 = sWc[(kk + 9) * 64 + ncol];
                    uint32_t bh0 = packhf(w0, w1), bh1 = packhf(w8, w9);
                    uint32_t bl0 = packhf(lo_of(w0), lo_of(w1));
                    uint32_t bl1 = packhf(lo_of(w8), lo_of(w9));
                    mma16816(pc, qah[kq][0], qah[kq][1], qah[kq][2], qah[kq][3], bh0, bh1);
                    mma16816(pc, qah[kq][0], qah[kq][1], qah[kq][2], qah[kq][3], bl0, bl1);
                    mma16816(pc, qal[kq][0], qal[kq][1], qal[kq][2], qal[kq][3], bh0, bh1);
                }
            }
            pah[kt2][0] = packhf(p0[0], p0[1]); pah[kt2][1] = packhf(p0[2], p0[3]);
            pah[kt2][2] = packhf(p1[0], p1[1]); pah[kt2][3] = packhf(p1[2], p1[3]);
            pal[kt2][0] = packhf(lo_of(p0[0]), lo_of(p0[1]));
            pal[kt2][1] = packhf(lo_of(p0[2]), lo_of(p0[3]));
            pal[kt2][2] = packhf(lo_of(p1[0]), lo_of(p1[1]));
            pal[kt2][3] = packhf(lo_of(p1[2]), lo_of(p1[3]));
        }
    }

    float m0 = -1e30f, m1 = -1e30f, s0 = 0.f, s1 = 0.f;

    // ================= PASS A: online (max,sum), hi-only =================
    #pragma unroll 1
    for (int ch = 0; ch < 8; ch++) {
        __syncthreads();
        {
            const uint4* srcH = (const uint4*)(g_QTH + (size_t)(bh * 8 + ch) * 4096);
            #pragma unroll
            for (int it = 0; it < 4; it++) {
                int idx = t + 256 * it;
                int j = idx >> 3, wg = idx & 7;
                *(uint4*)&QTH[j * 48 + wg * 4] = srcH[idx];
            }
        }
        __syncthreads();

        #pragma unroll
        for (int h2 = 0; h2 < 2; h2++) {
            float acc[8][4];
            #pragma unroll
            for (int nt = 0; nt < 8; nt++) {
                #pragma unroll
                for (int u = 0; u < 4; u++) acc[nt][u] = 0.f;
                const uint32_t* Brow = QTH + (8 * (h2 * 8 + nt) + grp) * 48 + q4 * 4;
                #pragma unroll
                for (int ktp = 0; ktp < 2; ktp++) {
                    uint4 bb = *(const uint4*)&Brow[ktp * 16];
                    mma16816(acc[nt], pah[2*ktp][0], pah[2*ktp][1], pah[2*ktp][2],
                             pah[2*ktp][3], bb.x, bb.y);
                    mma16816(acc[nt], pah[2*ktp+1][0], pah[2*ktp+1][1], pah[2*ktp+1][2],
                             pah[2*ktp+1][3], bb.z, bb.w);
                }
            }
            float cm0 = -1e30f, cm1 = -1e30f;
            #pragma unroll
            for (int nt = 0; nt < 8; nt++) {
                cm0 = fmaxf(cm0, fmaxf(acc[nt][0], acc[nt][1]));
                cm1 = fmaxf(cm1, fmaxf(acc[nt][2], acc[nt][3]));
            }
            cm0 = fmaxf(cm0, __shfl_xor_sync(0xffffffffu, cm0, 1));
            cm0 = fmaxf(cm0, __shfl_xor_sync(0xffffffffu, cm0, 2));
            cm1 = fmaxf(cm1, __shfl_xor_sync(0xffffffffu, cm1, 1));
            cm1 = fmaxf(cm1, __shfl_xor_sync(0xffffffffu, cm1, 2));
            float nm0 = fmaxf(m0, cm0), nm1 = fmaxf(m1, cm1);
            float sn0 = 0.f, sn1 = 0.f;
            #pragma unroll
            for (int nt = 0; nt < 8; nt++) {
                sn0 += __expf(acc[nt][0] - nm0) + __expf(acc[nt][1] - nm0);
                sn1 += __expf(acc[nt][2] - nm1) + __expf(acc[nt][3] - nm1);
            }
            sn0 += __shfl_xor_sync(0xffffffffu, sn0, 1);
            sn0 += __shfl_xor_sync(0xffffffffu, sn0, 2);
            sn1 += __shfl_xor_sync(0xffffffffu, sn1, 1);
            sn1 += __shfl_xor_sync(0xffffffffu, sn1, 2);
            s0 = s0 * __expf(m0 - nm0) + sn0;  m0 = nm0;
            s1 = s1 * __expf(m1 - nm1) + sn1;  m1 = nm1;
        }
    }
    const float is0 = 1.f / s0;
    const float is1 = 1.f / s1;

    // ================= PASS B: 2-term S, attn out, O += Ehi@V =================
    float oacc[8][4];
    #pragma unroll
    for (int nt = 0; nt < 8; nt++)
        #pragma unroll
        for (int u = 0; u < 4; u++) oacc[nt][u] = 0.f;

    #pragma unroll 1
    for (int ch = 0; ch < 8; ch++) {
        const int j0 = ch * 128;
        __syncthreads();
        {
            const size_t blob = (size_t)(bh * 8 + ch) * 4096;
            const uint4* sQH = (const uint4*)(g_QTH + blob);
            const uint4* sVH = (const uint4*)(g_VTH + blob);
            #pragma unroll
            for (int it = 0; it < 4; it++) {
                int idx = t + 256 * it;
                int j = idx >> 3, wg = idx & 7;
                *(uint4*)&QTH[j * 48 + wg * 4] = sQH[idx];
                int n = idx >> 4, wv = idx & 15;
                *(uint4*)&VTH[n * 72 + wv * 4] = sVH[idx];
            }
        }
        __syncthreads();

        #pragma unroll
        for (int h2 = 0; h2 < 2; h2++) {
            float acc[8][4];
            #pragma unroll
            for (int nt = 0; nt < 8; nt++) {
                #pragma unroll
                for (int u = 0; u < 4; u++) acc[nt][u] = 0.f;
                const uint32_t* Brow = QTH + (8 * (h2 * 8 + nt) + grp) * 48 + q4 * 4;
                #pragma unroll
                for (int ktp = 0; ktp < 2; ktp++) {
                    uint4 bb = *(const uint4*)&Brow[ktp * 16];
                    mma16816(acc[nt], pah[2*ktp][0], pah[2*ktp][1], pah[2*ktp][2],
                             pah[2*ktp][3], bb.x, bb.y);
                    mma16816(acc[nt], pal[2*ktp][0], pal[2*ktp][1], pal[2*ktp][2],
                             pal[2*ktp][3], bb.x, bb.y);
                    mma16816(acc[nt], pah[2*ktp+1][0], pah[2*ktp+1][1], pah[2*ktp+1][2],
                             pah[2*ktp+1][3], bb.z, bb.w);
                    mma16816(acc[nt], pal[2*ktp+1][0], pal[2*ktp+1][1], pal[2*ktp+1][2],
                             pal[2*ktp+1][3], bb.z, bb.w);
                }
            }

            #pragma unroll
            for (int kt2 = 0; kt2 < 4; kt2++) {
                const int t0 = 2 * kt2, t1 = 2 * kt2 + 1;
                float e00 = __expf(acc[t0][0] - m0);
                float e01 = __expf(acc[t0][1] - m0);
                float e02 = __expf(acc[t0][2] - m1);
                float e03 = __expf(acc[t0][3] - m1);
                float e10 = __expf(acc[t1][0] - m0);
                float e11 = __expf(acc[t1][1] - m0);
                float e12 = __expf(acc[t1][2] - m1);
                float e13 = __expf(acc[t1][3] - m1);

                const int cb = j0 + h2 * 64 + 16 * kt2 + 2 * q4;
                *(float2*)&attn_base[(size_t)rA * LK + cb]     = make_float2(e00 * is0, e01 * is0);
                *(float2*)&attn_base[(size_t)rB * LK + cb]     = make_float2(e02 * is1, e03 * is1);
                *(float2*)&attn_base[(size_t)rA * LK + cb + 8] = make_float2(e10 * is0, e11 * is0);
                *(float2*)&attn_base[(size_t)rB * LK + cb + 8] = make_float2(e12 * is1, e13 * is1);

                uint32_t eh0 = packhf(e00, e01), eh1 = packhf(e02, e03);
                uint32_t eh2 = packhf(e10, e11), eh3 = packhf(e12, e13);

                const int wv = h2 * 32 + kt2 * 8 + q4 * 2;
                #pragma unroll
                for (int nt = 0; nt < 8; nt++) {
                    uint2 vh = *(const uint2*)&VTH[(8 * nt + grp) * 72 + wv];
                    mma16816(oacc[nt], eh0, eh1, eh2, eh3, vh.x, vh.y);
                }
            }
        }
    }

    // ================= epilogue: scale by 1/sigma and store O =================
    #pragma unroll
    for (int nt = 0; nt < 8; nt++) {
        *(float2*)&out_base[(size_t)rA * DVv + 8 * nt + 2 * q4] =
            make_float2(oacc[nt][0] * is0, oacc[nt][1] * is0);
        *(float2*)&out_base[(size_t)rB * DVv + 8 * nt + 2 * q4] =
            make_float2(oacc[nt][2] * is1, oacc[nt][3] * is1);
    }
}

// ===================== launch =====================
extern "C" void kernel_launch(void* const* d_in, const int* in_sizes, int n_in,
                              void* d_out, int out_size) {
    const float* q   = (const float*)d_in[0];
    const float* WA  = (const float*)d_in[1];
    const float* WB  = (const float*)d_in[2];
    const float* WAt = (const float*)d_in[3];
    const float* WBt = (const float*)d_in[4];
    const float* qt  = (const float*)d_in[5];
    const float* v   = (const float*)d_in[6];

    float* outp = (float*)d_out;
    const size_t attn_elems = (size_t)Bz * Hh * LQ * LK;
    float* attn = outp + ((size_t)out_size - attn_elems);

    cudaFuncSetAttribute(attn_kernel, cudaFuncAttributeMaxDynamicSharedMemorySize,
                         SMEM_BYTES);

    pack_kernel<<<Bz * Hh * 8, 256>>>(qt, v);
    attn_kernel<<<Bz * Hh * 8, 256, SMEM_BYTES>>>(q, WA, WB, WBt, WAt, attn, outp);
}